// round 8
// baseline (speedup 1.0000x reference)
#include <cuda_runtime.h>
#include <math.h>

#define NN 100000
#define NE 3200000
#define F0 35
#define F0P 36
#define F1 64
#define SCAN_B 1024
#define NBLK ((NN + SCAN_B - 1) / SCAN_B)   // 98

// ---- scratch (device globals) ----
__device__ float g_dinv[NN];                       // 1/sqrt(weighted deg)
__device__ int   g_cnt[NN];                        // in-degree count
__device__ int   g_off[NN + 1];                    // CSR offsets
__device__ int   g_woff[NN];                       // working offsets for scatter
__device__ int   g_bsum[128];                      // per-block sums
__device__ int   g_boff[128];                      // per-block exclusive offsets
__device__ __align__(8) int2 g_edge[NE];           // CSR: (src, ew-bits) dst-sorted
__device__ __align__(16) float g_xpad[NN * F0P];   // x padded to 36 cols
__device__ __align__(16) float g_y[NN * F0P];      // dinv[n] * x[n]
__device__ __align__(8)  float g_h2s[NN * 2];      // dinv[n] * (relu(agg@W1+b1)@W2)

// K0: pad x, zero counts
__global__ void k_init(const float* __restrict__ x) {
    int idx = blockIdx.x * blockDim.x + threadIdx.x;
    if (idx >= NN * F0P) return;
    int n = idx / F0P;
    int f = idx - n * F0P;
    g_xpad[idx] = (f < F0) ? x[n * F0 + f] : 0.0f;
    if (f == 0) g_cnt[n] = 0;
}

// K1: in-degree count histogram
__global__ void k_hist(const int* __restrict__ ei) {
    int e = blockIdx.x * blockDim.x + threadIdx.x;
    if (e >= NE) return;
    atomicAdd(&g_cnt[ei[NE + e]], 1);
}

// K2a: per-block sums
__global__ void k_scan1() {
    __shared__ int s[SCAN_B];
    int n = blockIdx.x * SCAN_B + threadIdx.x;
    s[threadIdx.x] = (n < NN) ? g_cnt[n] : 0;
    __syncthreads();
    for (int o = SCAN_B / 2; o > 0; o >>= 1) {
        if (threadIdx.x < o) s[threadIdx.x] += s[threadIdx.x + o];
        __syncthreads();
    }
    if (threadIdx.x == 0) g_bsum[blockIdx.x] = s[0];
}

// K2b: scan of block sums
__global__ void k_scan2() {
    __shared__ int s[128];
    int t = threadIdx.x;
    int v = (t < NBLK) ? g_bsum[t] : 0;
    s[t] = v;
    __syncthreads();
    for (int o = 1; o < 128; o <<= 1) {
        int u = (t >= o) ? s[t - o] : 0;
        __syncthreads();
        s[t] += u;
        __syncthreads();
    }
    g_boff[t] = s[t] - v;
    if (t == NBLK - 1) g_off[NN] = s[t];
}

// K2c: block-local scan + offset
__global__ void k_scan3() {
    __shared__ int s[SCAN_B];
    int n = blockIdx.x * SCAN_B + threadIdx.x;
    int v = (n < NN) ? g_cnt[n] : 0;
    s[threadIdx.x] = v;
    __syncthreads();
    for (int o = 1; o < SCAN_B; o <<= 1) {
        int u = (threadIdx.x >= o) ? s[threadIdx.x - o] : 0;
        __syncthreads();
        s[threadIdx.x] += u;
        __syncthreads();
    }
    if (n < NN) {
        int excl = s[threadIdx.x] - v + g_boff[blockIdx.x];
        g_off[n] = excl;
        g_woff[n] = excl;
    }
}

// K3: scatter edges into CSR as packed {src, ew bits}
__global__ void k_scatter(const int* __restrict__ ei, const float* __restrict__ ew) {
    int e = blockIdx.x * blockDim.x + threadIdx.x;
    if (e >= NE) return;
    int s = ei[e];
    int d = ei[NE + e];
    int pos = atomicAdd(&g_woff[d], 1);
    g_edge[pos] = make_int2(s, __float_as_int(ew[e]));
}

// K4: fused deg+scale. 288 threads = 32 nodes. Phase A: dinv; Phase B: y = dinv*x.
__global__ void k_degscale() {
    __shared__ float sdinv[32];
    int base = blockIdx.x * 32;
    int tid = threadIdx.x;
    if (tid < 32) {
        int n = base + tid;
        if (n < NN) {
            int e = g_off[n], end = g_off[n + 1];
            float s = 1.0f;   // self-loop weight
            for (; e < end; e++) s += __int_as_float(g_edge[e].y);
            float di = rsqrtf(s);
            g_dinv[n] = di;
            sdinv[tid] = di;
        }
    }
    __syncthreads();
    int ni = tid / 9;
    int q = tid - ni * 9;
    int n = base + ni;
    if (n >= NN) return;
    float di = sdinv[ni];
    float4 v = ((const float4*)g_xpad)[n * 9 + q];
    ((float4*)g_y)[n * 9 + q] = make_float4(di * v.x, di * v.y, di * v.z, di * v.w);
}

// K5: FUSED layer-1: CSR aggregate (smem) -> GEMM 35->64 + b1 + relu -> @W2 -> h2s
// 288 threads/block = 32 nodes. Agg: 9 threads/node. GEMM: 8 threads/node x 8 out.
__global__ void k_fused1(const float* __restrict__ W1, const float* __restrict__ b1,
                         const float* __restrict__ W2) {
    __shared__ float sW[F0 * F1];     // 8960 B
    __shared__ float sb[F1];
    __shared__ float sW2[F1 * 2];
    __shared__ float sagg[32 * F0P];  // 4608 B
    __shared__ float sdinv[32];
    int tid = threadIdx.x;
    for (int i = tid; i < F0 * F1; i += 288) sW[i] = W1[i];
    if (tid < F1) sb[tid] = b1[tid];
    if (tid >= 128 && tid < 256) sW2[tid - 128] = W2[tid - 128];

    int base = blockIdx.x * 32;
    int ni = tid / 9;
    int q = tid - ni * 9;
    int n = base + ni;
    if (n < NN) {
        float di = g_dinv[n];
        if (q == 0) sdinv[ni] = di;
        const float4* yp = (const float4*)g_y;
        float4 acc = yp[n * 9 + q];           // self-loop term (y[n])
        int e = g_off[n], end = g_off[n + 1];
        for (; e < end; e++) {
            int2 ed = g_edge[e];
            float w = __int_as_float(ed.y);
            float4 v = yp[ed.x * 9 + q];
            acc.x += w * v.x; acc.y += w * v.y; acc.z += w * v.z; acc.w += w * v.w;
        }
        ((float4*)sagg)[ni * 9 + q] =
            make_float4(di * acc.x, di * acc.y, di * acc.z, di * acc.w);
    }
    __syncthreads();

    if (tid >= 256) return;
    int gi = tid >> 3;                 // node index 0..31
    int o0 = (tid & 7) * 8;            // output group
    int gn = base + gi;
    if (gn >= NN) return;
    float acc[8];
#pragma unroll
    for (int j = 0; j < 8; j++) acc[j] = sb[o0 + j];
    const float* xr = sagg + gi * F0P;
#pragma unroll
    for (int f = 0; f < F0; f++) {
        float xv = xr[f];
        const float* wr = sW + f * F1 + o0;
#pragma unroll
        for (int j = 0; j < 8; j++) acc[j] += xv * wr[j];
    }
    // relu then reduce to 2 outputs through W2
    float a0 = 0.0f, a1 = 0.0f;
#pragma unroll
    for (int j = 0; j < 8; j++) {
        float h = fmaxf(acc[j], 0.0f);
        a0 += h * sW2[(o0 + j) * 2 + 0];
        a1 += h * sW2[(o0 + j) * 2 + 1];
    }
    // reduce across the 8 lanes of this node (contiguous lanes, width 8)
#pragma unroll
    for (int o = 4; o > 0; o >>= 1) {
        a0 += __shfl_down_sync(0xFFFFFFFFu, a0, o, 8);
        a1 += __shfl_down_sync(0xFFFFFFFFu, a1, o, 8);
    }
    if ((tid & 7) == 0) {
        float di = sdinv[gi];
        ((float2*)g_h2s)[gn] = make_float2(di * a0, di * a1);
    }
}

// K6: layer-2 aggregation + bias + log_softmax, fused
__global__ void k_agg2out(const float* __restrict__ b2, float* __restrict__ out) {
    int n = blockIdx.x * blockDim.x + threadIdx.x;
    if (n >= NN) return;
    float di = g_dinv[n];
    const float2* hs = (const float2*)g_h2s;
    float2 h = hs[n];                         // self-loop
    float a0 = h.x, a1 = h.y;
    int e = g_off[n], end = g_off[n + 1];
    for (; e < end; e++) {
        int2 ed = g_edge[e];
        float w = __int_as_float(ed.y);
        float2 v = hs[ed.x];
        a0 += w * v.x;
        a1 += w * v.y;
    }
    a0 = di * a0 + b2[0];
    a1 = di * a1 + b2[1];
    float m = fmaxf(a0, a1);
    float lse = m + logf(expf(a0 - m) + expf(a1 - m));
    ((float2*)out)[n] = make_float2(a0 - lse, a1 - lse);
}

extern "C" void kernel_launch(void* const* d_in, const int* in_sizes, int n_in,
                              void* d_out, int out_size) {
    const float* x = nullptr;
    const int* ei = nullptr;
    const float* ew = nullptr;
    const float *W1 = nullptr, *b1 = nullptr, *W2 = nullptr, *b2 = nullptr;
    for (int i = 0; i < n_in; i++) {
        switch (in_sizes[i]) {
            case NN * F0:  x  = (const float*)d_in[i]; break;
            case 2 * NE:   ei = (const int*)d_in[i]; break;
            case NE:       ew = (const float*)d_in[i]; break;
            case F0 * F1:  W1 = (const float*)d_in[i]; break;
            case F1:       b1 = (const float*)d_in[i]; break;
            case F1 * 2:   W2 = (const float*)d_in[i]; break;
            case 2:        b2 = (const float*)d_in[i]; break;
            default: break;
        }
    }
    float* out = (float*)d_out;

    const int B = 256;
    const int NB32 = (NN + 31) / 32;   // 3125
    k_init<<<(NN * F0P + B - 1) / B, B>>>(x);
    k_hist<<<(NE + B - 1) / B, B>>>(ei);
    k_scan1<<<NBLK, SCAN_B>>>();
    k_scan2<<<1, 128>>>();
    k_scan3<<<NBLK, SCAN_B>>>();
    k_scatter<<<(NE + B - 1) / B, B>>>(ei, ew);
    k_degscale<<<NB32, 288>>>();
    k_fused1<<<NB32, 288>>>(W1, b1, W2);
    k_agg2out<<<(NN + B - 1) / B, B>>>(b2, out);
}

// round 12
// speedup vs baseline: 1.0643x; 1.0643x over previous
#include <cuda_runtime.h>
#include <math.h>

#define NN 100000
#define NE 3200000
#define F0 35
#define F0P 36
#define F1 64
#define SCAN_B 1024
#define NBLK ((NN + SCAN_B - 1) / SCAN_B)   // 98

// ---- scratch (device globals) ----
__device__ float g_dinv[NN];                       // 1/sqrt(weighted deg)
__device__ int   g_cnt[NN];                        // in-degree count
__device__ int   g_off[NN + 1];                    // CSR offsets
__device__ int   g_woff[NN];                       // working offsets for scatter
__device__ int   g_bsum[128];                      // per-block sums
__device__ int   g_boff[128];                      // per-block exclusive offsets
__device__ __align__(8) int2 g_edge[NE];           // CSR: (src, ew-bits) dst-sorted
__device__ __align__(16) float g_xpad[NN * F0P];   // x padded to 36 cols
__device__ __align__(16) float g_y[NN * F0P];      // dinv[n] * x[n]
__device__ __align__(16) float g_aggx[NN * F0P];   // layer-1 aggregate
__device__ __align__(8)  float g_h2s[NN * 2];      // dinv[n] * (relu(agg@W1+b1)@W2)

// K0: pad x, zero counts
__global__ void k_init(const float* __restrict__ x) {
    int idx = blockIdx.x * blockDim.x + threadIdx.x;
    if (idx >= NN * F0P) return;
    int n = idx / F0P;
    int f = idx - n * F0P;
    g_xpad[idx] = (f < F0) ? x[n * F0 + f] : 0.0f;
    if (f == 0) g_cnt[n] = 0;
}

// K1: in-degree count histogram
__global__ void k_hist(const int* __restrict__ ei) {
    int e = blockIdx.x * blockDim.x + threadIdx.x;
    if (e >= NE) return;
    atomicAdd(&g_cnt[ei[NE + e]], 1);
}

// K2a: per-block sums
__global__ void k_scan1() {
    __shared__ int s[SCAN_B];
    int n = blockIdx.x * SCAN_B + threadIdx.x;
    s[threadIdx.x] = (n < NN) ? g_cnt[n] : 0;
    __syncthreads();
    for (int o = SCAN_B / 2; o > 0; o >>= 1) {
        if (threadIdx.x < o) s[threadIdx.x] += s[threadIdx.x + o];
        __syncthreads();
    }
    if (threadIdx.x == 0) g_bsum[blockIdx.x] = s[0];
}

// K2b: scan of block sums
__global__ void k_scan2() {
    __shared__ int s[128];
    int t = threadIdx.x;
    int v = (t < NBLK) ? g_bsum[t] : 0;
    s[t] = v;
    __syncthreads();
    for (int o = 1; o < 128; o <<= 1) {
        int u = (t >= o) ? s[t - o] : 0;
        __syncthreads();
        s[t] += u;
        __syncthreads();
    }
    g_boff[t] = s[t] - v;
    if (t == NBLK - 1) g_off[NN] = s[t];
}

// K2c: block-local scan + offset
__global__ void k_scan3() {
    __shared__ int s[SCAN_B];
    int n = blockIdx.x * SCAN_B + threadIdx.x;
    int v = (n < NN) ? g_cnt[n] : 0;
    s[threadIdx.x] = v;
    __syncthreads();
    for (int o = 1; o < SCAN_B; o <<= 1) {
        int u = (threadIdx.x >= o) ? s[threadIdx.x - o] : 0;
        __syncthreads();
        s[threadIdx.x] += u;
        __syncthreads();
    }
    if (n < NN) {
        int excl = s[threadIdx.x] - v + g_boff[blockIdx.x];
        g_off[n] = excl;
        g_woff[n] = excl;
    }
}

// K3: scatter edges into CSR as packed {src, ew bits}
__global__ void k_scatter(const int* __restrict__ ei, const float* __restrict__ ew) {
    int e = blockIdx.x * blockDim.x + threadIdx.x;
    if (e >= NE) return;
    int s = ei[e];
    int d = ei[NE + e];
    int pos = atomicAdd(&g_woff[d], 1);
    g_edge[pos] = make_int2(s, __float_as_int(ew[e]));
}

// K4: fused deg+scale. 288 threads = 32 nodes.
__global__ void k_degscale() {
    __shared__ float sdinv[32];
    int base = blockIdx.x * 32;
    int tid = threadIdx.x;
    if (tid < 32) {
        int n = base + tid;
        if (n < NN) {
            int e = g_off[n], end = g_off[n + 1];
            float s = 1.0f;   // self-loop weight
            for (; e < end; e++) s += __int_as_float(g_edge[e].y);
            float di = rsqrtf(s);
            g_dinv[n] = di;
            sdinv[tid] = di;
        }
    }
    __syncthreads();
    int ni = tid / 9;
    int q = tid - ni * 9;
    int n = base + ni;
    if (n >= NN) return;
    float di = sdinv[ni];
    float4 v = ((const float4*)g_xpad)[n * 9 + q];
    ((float4*)g_y)[n * 9 + q] = make_float4(di * v.x, di * v.y, di * v.z, di * v.w);
}

// K5: layer-1 CSR aggregation (decoupled, load-balanced): 9 threads/node
__global__ void k_agg1() {
    int t = blockIdx.x * blockDim.x + threadIdx.x;
    if (t >= NN * 9) return;
    int n = t / 9;
    int q = t - n * 9;
    float di = g_dinv[n];
    const float4* yp = (const float4*)g_y;
    float4 acc = yp[n * 9 + q];               // self-loop term
    int e = g_off[n], end = g_off[n + 1];
    for (; e < end; e++) {
        int2 ed = g_edge[e];
        float w = __int_as_float(ed.y);
        float4 v = yp[ed.x * 9 + q];
        acc.x += w * v.x; acc.y += w * v.y; acc.z += w * v.z; acc.w += w * v.w;
    }
    ((float4*)g_aggx)[n * 9 + q] = make_float4(di * acc.x, di * acc.y, di * acc.z, di * acc.w);
}

// K6: FUSED GEMM1+relu+GEMM2: h2s = dinv * (relu(aggx@W1+b1) @ W2)
// 256 threads = 32 nodes x 8 threads, 8 outputs each, h1 stays in registers.
__global__ void k_gemm12(const float* __restrict__ W1, const float* __restrict__ b1,
                         const float* __restrict__ W2) {
    __shared__ float sW[F0 * F1];
    __shared__ float sb[F1];
    __shared__ float sW2[F1 * 2];
    __shared__ float sx[32 * F0P];
    int tid = threadIdx.x;
    for (int i = tid; i < F0 * F1; i += 256) sW[i] = W1[i];
    if (tid < F1) sb[tid] = b1[tid];
    if (tid >= 128 && tid < 256) sW2[tid - 128] = W2[tid - 128];
    int base = blockIdx.x * 32;
    const float4* ax = (const float4*)g_aggx;
    for (int i = tid; i < 32 * 9; i += 256) {
        int n = base + i / 9;
        ((float4*)sx)[i] = (n < NN) ? ax[n * 9 + (i % 9)]
                                    : make_float4(0.f, 0.f, 0.f, 0.f);
    }
    __syncthreads();
    int gi = tid >> 3;
    int o0 = (tid & 7) * 8;
    int n = base + gi;
    if (n >= NN) return;
    float acc[8];
#pragma unroll
    for (int j = 0; j < 8; j++) acc[j] = sb[o0 + j];
    const float* xr = sx + gi * F0P;
#pragma unroll
    for (int f = 0; f < F0; f++) {
        float xv = xr[f];
        const float* wr = sW + f * F1 + o0;
#pragma unroll
        for (int j = 0; j < 8; j++) acc[j] += xv * wr[j];
    }
    float a0 = 0.0f, a1 = 0.0f;
#pragma unroll
    for (int j = 0; j < 8; j++) {
        float h = fmaxf(acc[j], 0.0f);
        a0 += h * sW2[(o0 + j) * 2 + 0];
        a1 += h * sW2[(o0 + j) * 2 + 1];
    }
#pragma unroll
    for (int o = 4; o > 0; o >>= 1) {
        a0 += __shfl_down_sync(0xFFFFFFFFu, a0, o, 8);
        a1 += __shfl_down_sync(0xFFFFFFFFu, a1, o, 8);
    }
    if ((tid & 7) == 0) {
        float di = g_dinv[n];
        ((float2*)g_h2s)[n] = make_float2(di * a0, di * a1);
    }
}

// K7: layer-2 aggregation + bias + log_softmax, fused
__global__ void k_agg2out(const float* __restrict__ b2, float* __restrict__ out) {
    int n = blockIdx.x * blockDim.x + threadIdx.x;
    if (n >= NN) return;
    float di = g_dinv[n];
    const float2* hs = (const float2*)g_h2s;
    float2 h = hs[n];                         // self-loop
    float a0 = h.x, a1 = h.y;
    int e = g_off[n], end = g_off[n + 1];
    for (; e < end; e++) {
        int2 ed = g_edge[e];
        float w = __int_as_float(ed.y);
        float2 v = hs[ed.x];
        a0 += w * v.x;
        a1 += w * v.y;
    }
    a0 = di * a0 + b2[0];
    a1 = di * a1 + b2[1];
    float m = fmaxf(a0, a1);
    float lse = m + logf(expf(a0 - m) + expf(a1 - m));
    ((float2*)out)[n] = make_float2(a0 - lse, a1 - lse);
}

extern "C" void kernel_launch(void* const* d_in, const int* in_sizes, int n_in,
                              void* d_out, int out_size) {
    const float* x = nullptr;
    const int* ei = nullptr;
    const float* ew = nullptr;
    const float *W1 = nullptr, *b1 = nullptr, *W2 = nullptr, *b2 = nullptr;
    for (int i = 0; i < n_in; i++) {
        switch (in_sizes[i]) {
            case NN * F0:  x  = (const float*)d_in[i]; break;
            case 2 * NE:   ei = (const int*)d_in[i]; break;
            case NE:       ew = (const float*)d_in[i]; break;
            case F0 * F1:  W1 = (const float*)d_in[i]; break;
            case F1:       b1 = (const float*)d_in[i]; break;
            case F1 * 2:   W2 = (const float*)d_in[i]; break;
            case 2:        b2 = (const float*)d_in[i]; break;
            default: break;
        }
    }
    float* out = (float*)d_out;

    const int B = 256;
    const int NB32 = (NN + 31) / 32;   // 3125
    k_init<<<(NN * F0P + B - 1) / B, B>>>(x);
    k_hist<<<(NE + B - 1) / B, B>>>(ei);
    k_scan1<<<NBLK, SCAN_B>>>();
    k_scan2<<<1, 128>>>();
    k_scan3<<<NBLK, SCAN_B>>>();
    k_scatter<<<(NE + B - 1) / B, B>>>(ei, ew);
    k_degscale<<<NB32, 288>>>();
    k_agg1<<<(NN * 9 + B - 1) / B, B>>>();
    k_gemm12<<<NB32, 256>>>(W1, b1, W2);
    k_agg2out<<<(NN + B - 1) / B, B>>>(b2, out);
}